// round 1
// baseline (speedup 1.0000x reference)
#include <cuda_runtime.h>
#include <math.h>

#define BB 32
#define SS 512
#define DD 512
#define HH 8
#define DFF 64
#define SCP 516   // padded score-row stride (words)

// Scratch (allocation-free): 4 x 33.5 MB
__device__ float g_QH[BB*HH*SS*DFF];
__device__ float g_KH[BB*HH*SS*DFF];
__device__ float g_VH[BB*HH*SS*DFF];
__device__ float g_CT[BB*SS*DD];

// ---------------------------------------------------------------------------
// C[r,c] = sum_k A[r,k]*W[c,k] + bias[c]   (NT GEMM, M=16384,N=512,K=512)
// MODE 0: A := g_CT, write C row-major (final projection)
// MODE 1/2/3: A param, write head-split into g_QH/g_KH/g_VH
// ---------------------------------------------------------------------------
template<int MODE>
__global__ __launch_bounds__(256)
void sgemm_nt_kernel(const float* __restrict__ A,
                     const float* __restrict__ W,
                     const float* __restrict__ bias,
                     float* __restrict__ C)
{
    __shared__ float As[16][68];
    __shared__ float Ws[16][68];
    const int tid = threadIdx.x;
    const int tx = tid & 15, ty = tid >> 4;
    const int rBase = blockIdx.x * 64;
    const int cBase = blockIdx.y * 64;
    const int lr = tid >> 2;           // 0..63
    const int lk = (tid & 3) << 2;     // 0,4,8,12
    const float* Asrc = (MODE == 0) ? g_CT : A;
    const float* Ap = Asrc + (size_t)(rBase + lr) * DD + lk;
    const float* Wp = W    + (size_t)(cBase + lr) * DD + lk;

    float acc[4][4];
    #pragma unroll
    for (int i = 0; i < 4; i++)
        #pragma unroll
        for (int j = 0; j < 4; j++) acc[i][j] = 0.f;

    for (int k0 = 0; k0 < DD; k0 += 16) {
        float4 a4 = *(const float4*)(Ap + k0);
        float4 w4 = *(const float4*)(Wp + k0);
        __syncthreads();
        As[lk+0][lr] = a4.x; As[lk+1][lr] = a4.y; As[lk+2][lr] = a4.z; As[lk+3][lr] = a4.w;
        Ws[lk+0][lr] = w4.x; Ws[lk+1][lr] = w4.y; Ws[lk+2][lr] = w4.z; Ws[lk+3][lr] = w4.w;
        __syncthreads();
        #pragma unroll
        for (int kk = 0; kk < 16; kk++) {
            float av[4], wv[4];
            #pragma unroll
            for (int i = 0; i < 4; i++) av[i] = As[kk][ty*4+i];
            #pragma unroll
            for (int j = 0; j < 4; j++) wv[j] = Ws[kk][tx*4+j];
            #pragma unroll
            for (int i = 0; i < 4; i++)
                #pragma unroll
                for (int j = 0; j < 4; j++)
                    acc[i][j] = fmaf(av[i], wv[j], acc[i][j]);
        }
    }

    const int c0 = cBase + tx*4;
    const float4 bi = *(const float4*)(bias + c0);
    #pragma unroll
    for (int i = 0; i < 4; i++) {
        int r = rBase + ty*4 + i;
        float4 o;
        o.x = acc[i][0] + bi.x;
        o.y = acc[i][1] + bi.y;
        o.z = acc[i][2] + bi.z;
        o.w = acc[i][3] + bi.w;
        if (MODE == 0) {
            *(float4*)(C + (size_t)r * DD + c0) = o;
        } else {
            int b_ = r >> 9, s_ = r & (SS-1);
            int h_ = c0 >> 6, df_ = c0 & (DFF-1);
            float* dst = (MODE == 1) ? g_QH : (MODE == 2) ? g_KH : g_VH;
            *(float4*)(dst + (((size_t)(b_*HH + h_) * SS + s_) * DFF + df_)) = o;
        }
    }
}

// ---------------------------------------------------------------------------
// Fused attention per (b,h, 32 q-rows). 256 threads.
// smem: Qs[32*64] | SC[32*516] | KV[8192] (K-transposed 64x128 / V 64x72)
// ---------------------------------------------------------------------------
__global__ __launch_bounds__(256)
void akt_attn_kernel(const float* __restrict__ qd,
                     const float* __restrict__ gammas,
                     const int* __restrict__ zero_pad)
{
    extern __shared__ float sm[];
    float* Qs = sm;                    // 2048 floats
    float* SC = sm + 2048;             // 16512 floats
    float* KV = sm + 2048 + 16512;     // 8192 floats

    const int tid = threadIdx.x;
    const int bh = blockIdx.y;
    const int b  = bh >> 3;
    const int h  = bh & 7;
    const int q0 = blockIdx.x << 5;
    const int qmax = q0 + 31;

    const float* QH = g_QH + (size_t)bh * SS * DFF;
    const float* KH = g_KH + (size_t)bh * SS * DFF;
    const float* VH = g_VH + (size_t)bh * SS * DFF;

    // ---- load Q tile, pre-scaled by 1/sqrt(64) ----
    #pragma unroll
    for (int u = 0; u < 2; u++) {
        int idx = tid + u * 256;          // float4 index, 512 total
        int r  = idx >> 4;
        int c4 = (idx & 15) << 2;
        float4 qv = *(const float4*)(QH + (size_t)(q0 + r) * DFF + c4);
        qv.x *= 0.125f; qv.y *= 0.125f; qv.z *= 0.125f; qv.w *= 0.125f;
        *(float4*)(Qs + r * DFF + c4) = qv;
    }

    // ---- Phase 1: scores = (Q/8) K^T  (causal-pruned j-tiles of 128) ----
    const int qb1 = (tid >> 5) << 2;      // 4 q rows per thread
    const int jb1 = (tid & 31) << 2;      // 4 j cols per thread
    const int njt = (qmax >> 7) + 1;
    for (int jt = 0; jt < njt; jt++) {
        const int j0 = jt << 7;
        __syncthreads();
        {   // load K tile transposed: KV[df*128 + j]
            int jr  = tid >> 1;           // 0..127
            int df0 = (tid & 1) << 5;     // 0 or 32
            const float* kp = KH + (size_t)(j0 + jr) * DFF + df0;
            #pragma unroll
            for (int u = 0; u < 8; u++) {
                float4 k4 = *(const float4*)(kp + (u << 2));
                int dfb = df0 + (u << 2);
                KV[(dfb+0)*128 + jr] = k4.x;
                KV[(dfb+1)*128 + jr] = k4.y;
                KV[(dfb+2)*128 + jr] = k4.z;
                KV[(dfb+3)*128 + jr] = k4.w;
            }
        }
        __syncthreads();
        float acc[4][4];
        #pragma unroll
        for (int i = 0; i < 4; i++)
            #pragma unroll
            for (int j = 0; j < 4; j++) acc[i][j] = 0.f;
        #pragma unroll
        for (int df = 0; df < 64; df++) {
            float4 k4 = *(const float4*)(KV + df*128 + jb1);
            float qv0 = Qs[(qb1+0)*64 + df];
            float qv1 = Qs[(qb1+1)*64 + df];
            float qv2 = Qs[(qb1+2)*64 + df];
            float qv3 = Qs[(qb1+3)*64 + df];
            acc[0][0]=fmaf(qv0,k4.x,acc[0][0]); acc[0][1]=fmaf(qv0,k4.y,acc[0][1]);
            acc[0][2]=fmaf(qv0,k4.z,acc[0][2]); acc[0][3]=fmaf(qv0,k4.w,acc[0][3]);
            acc[1][0]=fmaf(qv1,k4.x,acc[1][0]); acc[1][1]=fmaf(qv1,k4.y,acc[1][1]);
            acc[1][2]=fmaf(qv1,k4.z,acc[1][2]); acc[1][3]=fmaf(qv1,k4.w,acc[1][3]);
            acc[2][0]=fmaf(qv2,k4.x,acc[2][0]); acc[2][1]=fmaf(qv2,k4.y,acc[2][1]);
            acc[2][2]=fmaf(qv2,k4.z,acc[2][2]); acc[2][3]=fmaf(qv2,k4.w,acc[2][3]);
            acc[3][0]=fmaf(qv3,k4.x,acc[3][0]); acc[3][1]=fmaf(qv3,k4.y,acc[3][1]);
            acc[3][2]=fmaf(qv3,k4.z,acc[3][2]); acc[3][3]=fmaf(qv3,k4.w,acc[3][3]);
        }
        #pragma unroll
        for (int i = 0; i < 4; i++) {
            float4 o = make_float4(acc[i][0], acc[i][1], acc[i][2], acc[i][3]);
            *(float4*)(SC + (qb1+i)*SCP + j0 + jb1) = o;
        }
    }
    __syncthreads();

    // ---- Phase 2: softmax1 -> cumsum -> decay -> rescale -> softmax2 ----
    const int lane = tid & 31;
    const int w    = tid >> 5;
    const float gamma = -log1pf(__expf(gammas[h]));   // -softplus
    const int zp = *zero_pad;

    for (int pass = 0; pass < 4; pass++) {
        const int qr = (pass << 3) + w;   // warp per row
        const int qg = q0 + qr;
        float sv[16], pv[16];
        #pragma unroll
        for (int i = 0; i < 16; i++) sv[i] = SC[qr*SCP + (i<<5) + lane];

        // softmax 1 (causal mask j<=qg)
        float m = -3.0e38f;
        #pragma unroll
        for (int i = 0; i < 16; i++) {
            int j = (i<<5) + lane;
            if (j <= qg) m = fmaxf(m, sv[i]);
        }
        #pragma unroll
        for (int off = 16; off > 0; off >>= 1)
            m = fmaxf(m, __shfl_xor_sync(0xffffffffu, m, off));
        float ssum = 0.f;
        #pragma unroll
        for (int i = 0; i < 16; i++) {
            int j = (i<<5) + lane;
            pv[i] = (j <= qg) ? __expf(sv[i] - m) : 0.f;
            ssum += pv[i];
        }
        #pragma unroll
        for (int off = 16; off > 0; off >>= 1)
            ssum += __shfl_xor_sync(0xffffffffu, ssum, off);
        const float inv1 = 1.f / ssum;

        // sequential-chunk cumsum + decay (disttot == 1 exactly)
        float carry = 0.f;
        const float* qdrow = qd + ((size_t)b * SS + qg) * SS;
        #pragma unroll
        for (int i = 0; i < 16; i++) {
            int j = (i<<5) + lane;
            float s = pv[i] * inv1;
            #pragma unroll
            for (int off = 1; off < 32; off <<= 1) {
                float t = __shfl_up_sync(0xffffffffu, s, off);
                if (lane >= off) s += t;
            }
            float tot = __shfl_sync(0xffffffffu, s, 31);
            float c = carry + s;          // inclusive cumsum
            carry += tot;
            float rem = fmaxf(1.f - c, 0.f);
            float dsc = (j <= qg) ? sqrtf(rem * (float)(qg - j)) : 0.f;
            float qdv = qdrow[j];
            float sig = 1.f / (1.f + __expf(-qdv));
            float diffv = __expf(sig);
            float te = __expf(dsc * gamma * diffv);
            te = fminf(fmaxf(te, 1e-5f), 1e5f);
            pv[i] = (j <= qg) ? sv[i] * te : -3.0e38f;
        }

        // softmax 2
        float m2 = -3.0e38f;
        #pragma unroll
        for (int i = 0; i < 16; i++) m2 = fmaxf(m2, pv[i]);
        #pragma unroll
        for (int off = 16; off > 0; off >>= 1)
            m2 = fmaxf(m2, __shfl_xor_sync(0xffffffffu, m2, off));
        float sum2 = 0.f;
        #pragma unroll
        for (int i = 0; i < 16; i++) {
            int j = (i<<5) + lane;
            float e = (j <= qg) ? __expf(pv[i] - m2) : 0.f;
            sv[i] = e;
            sum2 += e;
        }
        #pragma unroll
        for (int off = 16; off > 0; off >>= 1)
            sum2 += __shfl_xor_sync(0xffffffffu, sum2, off);
        const float inv2 = 1.f / sum2;
        const bool zrow = (zp != 0) && (qg == 0);
        #pragma unroll
        for (int i = 0; i < 16; i++)
            SC[qr*SCP + (i<<5) + lane] = zrow ? 0.f : sv[i] * inv2;
    }

    // ---- Phase 3: out = P @ V, store into concat layout [B,S,D] ----
    const int qb3 = (tid >> 4) << 1;      // 2 q rows
    const int df3 = (tid & 15) << 2;      // 4 df cols
    float o0[4] = {0.f,0.f,0.f,0.f};
    float o1[4] = {0.f,0.f,0.f,0.f};
    const int nvt = (qmax >> 6) + 1;      // causal-pruned V tiles of 64
    for (int jt = 0; jt < nvt; jt++) {
        __syncthreads();
        {   // load V tile: KV[j*72 + df]
            int jr  = tid >> 2;           // 0..63
            int df0 = (tid & 3) << 4;
            const float* vp = VH + (size_t)((jt<<6) + jr) * DFF + df0;
            #pragma unroll
            for (int u = 0; u < 4; u++) {
                float4 v4 = *(const float4*)(vp + (u<<2));
                *(float4*)(KV + jr*72 + df0 + (u<<2)) = v4;
            }
        }
        __syncthreads();
        const int j0 = jt << 6;
        #pragma unroll 8
        for (int jj = 0; jj < 64; jj++) {
            float p0 = SC[(qb3+0)*SCP + j0 + jj];
            float p1 = SC[(qb3+1)*SCP + j0 + jj];
            float4 v4 = *(const float4*)(KV + jj*72 + df3);
            o0[0]=fmaf(p0,v4.x,o0[0]); o0[1]=fmaf(p0,v4.y,o0[1]);
            o0[2]=fmaf(p0,v4.z,o0[2]); o0[3]=fmaf(p0,v4.w,o0[3]);
            o1[0]=fmaf(p1,v4.x,o1[0]); o1[1]=fmaf(p1,v4.y,o1[1]);
            o1[2]=fmaf(p1,v4.z,o1[2]); o1[3]=fmaf(p1,v4.w,o1[3]);
        }
    }
    {
        int qg0 = q0 + qb3;
        float4 a = make_float4(o0[0], o0[1], o0[2], o0[3]);
        float4 c = make_float4(o1[0], o1[1], o1[2], o1[3]);
        *(float4*)(g_CT + ((size_t)(b * SS + qg0    ) * DD) + (h << 6) + df3) = a;
        *(float4*)(g_CT + ((size_t)(b * SS + qg0 + 1) * DD) + (h << 6) + df3) = c;
    }
}

// ---------------------------------------------------------------------------
extern "C" void kernel_launch(void* const* d_in, const int* in_sizes, int n_in,
                              void* d_out, int out_size)
{
    const float* q      = (const float*)d_in[0];
    const float* k      = (const float*)d_in[1];
    const float* v      = (const float*)d_in[2];
    // d_in[3] = mask (causal tril, hard-assumed)
    const int*   zero_pad = (const int*)d_in[4];
    const float* qd     = (const float*)d_in[5];
    const float* Wk     = (const float*)d_in[6];
    const float* bk     = (const float*)d_in[7];
    const float* Wv     = (const float*)d_in[8];
    const float* bv     = (const float*)d_in[9];
    const float* Wo     = (const float*)d_in[10];
    const float* bo     = (const float*)d_in[11];
    const float* gammas = (const float*)d_in[12];
    float* out = (float*)d_out;

    const int ATTN_SMEM = (2048 + 16512 + 8192) * 4;   // 107008 B
    cudaFuncSetAttribute(akt_attn_kernel,
                         cudaFuncAttributeMaxDynamicSharedMemorySize, ATTN_SMEM);

    dim3 gProj(256, 8);
    sgemm_nt_kernel<1><<<gProj, 256>>>(q, Wk, bk, nullptr);   // QH (key_linear)
    sgemm_nt_kernel<2><<<gProj, 256>>>(k, Wk, bk, nullptr);   // KH
    sgemm_nt_kernel<3><<<gProj, 256>>>(v, Wv, bv, nullptr);   // VH

    akt_attn_kernel<<<dim3(16, 256), 256, ATTN_SMEM>>>(qd, gammas, zero_pad);

    sgemm_nt_kernel<0><<<gProj, 256>>>(nullptr, Wo, bo, out); // final proj
}

// round 7
// speedup vs baseline: 1.5005x; 1.5005x over previous
#include <cuda_runtime.h>
#include <cuda_bf16.h>
#include <stdint.h>
#include <math.h>

#define BB 32
#define SS 512
#define DD 512
#define HH 8
#define DFF 64
#define SCP 516   // padded score-row stride (words)

// Scratch (allocation-free)
__device__ float g_QH[BB*HH*SS*DFF];
__device__ float g_KH[BB*HH*SS*DFF];
__device__ float g_VH[BB*HH*SS*DFF];
__device__ float g_CT[BB*SS*DD];

// bf16 hi/lo split operand buffers
__device__ __nv_bfloat16 g_Ah[3][BB*SS*DD];
__device__ __nv_bfloat16 g_Al[3][BB*SS*DD];
__device__ __nv_bfloat16 g_Wh[3][DD*DD];
__device__ __nv_bfloat16 g_Wl[3][DD*DD];

// ===========================================================================
// PTX helpers (portable sm_80+ subset: ldmatrix / mma.sync / cp.async)
// ===========================================================================
__device__ __forceinline__ unsigned int smem_to_u32(const void* p) {
    unsigned int a;
    asm("{ .reg .u64 t; cvta.to.shared.u64 t, %1; cvt.u32.u64 %0, t; }"
        : "=r"(a) : "l"(p));
    return a;
}

__device__ __forceinline__ void cp_async16(unsigned int dst, const void* src) {
    asm volatile("cp.async.cg.shared.global [%0], [%1], 16;\n"
                 :: "r"(dst), "l"(src));
}
#define CP_COMMIT() asm volatile("cp.async.commit_group;\n" ::: "memory")
#define CP_WAIT1()  asm volatile("cp.async.wait_group 1;\n" ::: "memory")

__device__ __forceinline__ void ldmatrix_x4(unsigned int* r, unsigned int addr) {
    asm volatile("ldmatrix.sync.aligned.m8n8.x4.shared.b16 {%0,%1,%2,%3}, [%4];"
                 : "=r"(r[0]), "=r"(r[1]), "=r"(r[2]), "=r"(r[3]) : "r"(addr));
}

__device__ __forceinline__ void mma_bf16(float* c, const unsigned int* a,
                                         unsigned int b0, unsigned int b1) {
    asm volatile(
        "mma.sync.aligned.m16n8k16.row.col.f32.bf16.bf16.f32 "
        "{%0,%1,%2,%3}, {%4,%5,%6,%7}, {%8,%9}, {%0,%1,%2,%3};"
        : "+f"(c[0]), "+f"(c[1]), "+f"(c[2]), "+f"(c[3])
        : "r"(a[0]), "r"(a[1]), "r"(a[2]), "r"(a[3]), "r"(b0), "r"(b1));
}

__device__ __forceinline__ unsigned int bfpack(float x, float y) {
    __nv_bfloat16 h0 = __float2bfloat16(x), h1 = __float2bfloat16(y);
    return (unsigned int)__bfloat16_as_ushort(h0) |
           ((unsigned int)__bfloat16_as_ushort(h1) << 16);
}

// ===========================================================================
// Convert fp32 -> bf16 hi/lo split.  which: 0-2 inputs->g_Ah/l, 3-5 weights,
// 6: g_CT -> g_Ah[0]/g_Al[0].  n multiple of 2048.
// ===========================================================================
__global__ __launch_bounds__(256)
void convert_split(const float* __restrict__ src_in, int which, int n)
{
    const float* src = (which == 6) ? g_CT : src_in;
    __nv_bfloat16 *hi, *lo;
    if (which < 3)      { hi = g_Ah[which];   lo = g_Al[which]; }
    else if (which < 6) { hi = g_Wh[which-3]; lo = g_Wl[which-3]; }
    else                { hi = g_Ah[0];       lo = g_Al[0]; }

    int idx = (blockIdx.x * 256 + threadIdx.x) << 3;
    if (idx >= n) return;
    float4 a = *(const float4*)(src + idx);
    float4 b = *(const float4*)(src + idx + 4);
    float v[8] = {a.x, a.y, a.z, a.w, b.x, b.y, b.z, b.w};
    unsigned int hw[4], lw[4];
    #pragma unroll
    for (int i = 0; i < 4; i++) {
        float x = v[2*i], y = v[2*i+1];
        __nv_bfloat16 h0 = __float2bfloat16(x), h1 = __float2bfloat16(y);
        float r0 = x - __bfloat162float(h0), r1 = y - __bfloat162float(h1);
        hw[i] = (unsigned int)__bfloat16_as_ushort(h0) |
                ((unsigned int)__bfloat16_as_ushort(h1) << 16);
        lw[i] = bfpack(r0, r1);
    }
    *(uint4*)(hi + idx) = make_uint4(hw[0], hw[1], hw[2], hw[3]);
    *(uint4*)(lo + idx) = make_uint4(lw[0], lw[1], lw[2], lw[3]);
}

// ===========================================================================
// mma.sync bf16 3-term split GEMM: C[m,n] = sum_k A[m,k]*W[n,k] + bias[n]
// Tile 128x128, BK=32, 3-stage cp.async, 8 warps (4m x 2n), warp 32x64.
// MODE 0: A=split(g_CT), W=Wo -> Cout row-major
// MODE 1: z in {0,1,2} = q,k,v -> g_QH/g_KH/g_VH head-split
// ===========================================================================
#define STG_STRIDE 32768    // 4 arrays * 8192 B
#define AH_OFF 0
#define AL_OFF 8192
#define BH_OFF 16384
#define BL_OFF 24576

__device__ __forceinline__ void load_stage(
    const __nv_bfloat16* __restrict__ Ah, const __nv_bfloat16* __restrict__ Al,
    const __nv_bfloat16* __restrict__ Bh, const __nv_bfloat16* __restrict__ Bl,
    unsigned int st, int rBase, int cBase, int kt, int tid)
{
    #pragma unroll
    for (int i = 0; i < 2; i++) {
        int c   = tid * 2 + i;          // 0..511 chunk id
        int row = c >> 2;
        int kc  = c & 3;
        unsigned int dsw = (unsigned int)(row * 64) +
                           (unsigned int)((kc ^ ((row >> 1) & 3)) << 4);
        size_t aoff = (size_t)(rBase + row) * DD + kt * 32 + kc * 8;
        size_t boff = (size_t)(cBase + row) * DD + kt * 32 + kc * 8;
        cp_async16(st + AH_OFF + dsw, Ah + aoff);
        cp_async16(st + AL_OFF + dsw, Al + aoff);
        cp_async16(st + BH_OFF + dsw, Bh + boff);
        cp_async16(st + BL_OFF + dsw, Bl + boff);
    }
}

template<int MODE>
__global__ __launch_bounds__(256)
void gemm_mma_kernel(const float* __restrict__ bias0,
                     const float* __restrict__ bias1,
                     float* __restrict__ Cout)
{
    extern __shared__ char smem[];
    const unsigned int sb = smem_to_u32(smem);
    const int tid  = threadIdx.x;
    const int lane = tid & 31;
    const int wid  = tid >> 5;
    const int warp_m = wid & 3;        // 4 m-warps
    const int warp_n = wid >> 2;       // 2 n-warps
    const int rBase = blockIdx.x << 7;
    const int cBase = blockIdx.y << 7;
    const int z = blockIdx.z;

    const __nv_bfloat16 *Ah, *Al, *Bh, *Bl;
    const float* bias;
    if (MODE == 0) {
        Ah = g_Ah[0]; Al = g_Al[0]; Bh = g_Wh[2]; Bl = g_Wl[2]; bias = bias0;
    } else {
        Ah = g_Ah[z]; Al = g_Al[z];
        int wi = (z == 2) ? 1 : 0;
        Bh = g_Wh[wi]; Bl = g_Wl[wi];
        bias = (z == 2) ? bias1 : bias0;
    }

    float acc[2][8][4];
    #pragma unroll
    for (int mf = 0; mf < 2; mf++)
        #pragma unroll
        for (int nf = 0; nf < 8; nf++)
            #pragma unroll
            for (int i = 0; i < 4; i++) acc[mf][nf][i] = 0.f;

    load_stage(Ah, Al, Bh, Bl, sb,              rBase, cBase, 0, tid); CP_COMMIT();
    load_stage(Ah, Al, Bh, Bl, sb + STG_STRIDE, rBase, cBase, 1, tid); CP_COMMIT();

    for (int kt = 0; kt < 16; kt++) {
        CP_WAIT1();
        __syncthreads();
        if (kt + 2 < 16)
            load_stage(Ah, Al, Bh, Bl, sb + ((kt + 2) % 3) * STG_STRIDE,
                       rBase, cBase, kt + 2, tid);
        CP_COMMIT();

        const unsigned int stB = sb + (kt % 3) * STG_STRIDE;
        #pragma unroll
        for (int ks = 0; ks < 2; ks++) {
            unsigned int ah[2][4], al[2][4], bh[4][4], bl[4][4];
            #pragma unroll
            for (int mf = 0; mf < 2; mf++) {
                int row = warp_m * 32 + mf * 16 + (lane & 15);
                int kchunk = ks * 2 + (lane >> 4);
                unsigned int ad = stB + (unsigned int)(row * 64) +
                    (unsigned int)((kchunk ^ ((row >> 1) & 3)) << 4);
                ldmatrix_x4(ah[mf], ad + AH_OFF);
                ldmatrix_x4(al[mf], ad + AL_OFF);
            }
            #pragma unroll
            for (int p = 0; p < 4; p++) {
                int row = warp_n * 64 + p * 16 + (lane & 7) + ((lane & 16) >> 1);
                int kchunk = ks * 2 + ((lane >> 3) & 1);
                unsigned int bd = stB + (unsigned int)(row * 64) +
                    (unsigned int)((kchunk ^ ((row >> 1) & 3)) << 4);
                ldmatrix_x4(bh[p], bd + BH_OFF);
                ldmatrix_x4(bl[p], bd + BL_OFF);
            }
            #pragma unroll
            for (int mf = 0; mf < 2; mf++)
                #pragma unroll
                for (int nf = 0; nf < 8; nf++) {
                    int p = nf >> 1, hh = (nf & 1) * 2;
                    mma_bf16(acc[mf][nf], ah[mf], bh[p][hh], bh[p][hh+1]);
                    mma_bf16(acc[mf][nf], ah[mf], bl[p][hh], bl[p][hh+1]);
                    mma_bf16(acc[mf][nf], al[mf], bh[p][hh], bh[p][hh+1]);
                }
        }
    }

    // Epilogue
    #pragma unroll
    for (int mf = 0; mf < 2; mf++) {
        #pragma unroll
        for (int nf = 0; nf < 8; nf++) {
            int col = cBase + warp_n * 64 + nf * 8 + (lane & 3) * 2;
            int row = rBase + warp_m * 32 + mf * 16 + (lane >> 2);
            float b0 = bias[col], b1 = bias[col + 1];
            float2 v0 = make_float2(acc[mf][nf][0] + b0, acc[mf][nf][1] + b1);
            float2 v1 = make_float2(acc[mf][nf][2] + b0, acc[mf][nf][3] + b1);
            if (MODE == 0) {
                *(float2*)(Cout + (size_t)row * DD + col) = v0;
                *(float2*)(Cout + (size_t)(row + 8) * DD + col) = v1;
            } else {
                int h = col >> 6, df = col & 63;
                float* dst = (z == 0) ? g_QH : (z == 1) ? g_KH : g_VH;
                int b_ = row >> 9, s_ = row & (SS - 1);
                *(float2*)(dst + (((size_t)(b_ * HH + h) * SS + s_) * DFF + df)) = v0;
                *(float2*)(dst + (((size_t)(b_ * HH + h) * SS + s_ + 8) * DFF + df)) = v1;
            }
        }
    }
}

// ---------------------------------------------------------------------------
// Fused attention per (b,h, 32 q-rows). 256 threads.  (unchanged from R1)
// ---------------------------------------------------------------------------
__global__ __launch_bounds__(256)
void akt_attn_kernel(const float* __restrict__ qd,
                     const float* __restrict__ gammas,
                     const int* __restrict__ zero_pad)
{
    extern __shared__ float sm[];
    float* Qs = sm;                    // 2048 floats
    float* SC = sm + 2048;             // 16512 floats
    float* KV = sm + 2048 + 16512;     // 8192 floats

    const int tid = threadIdx.x;
    const int bh = blockIdx.y;
    const int b  = bh >> 3;
    const int h  = bh & 7;
    const int q0 = blockIdx.x << 5;
    const int qmax = q0 + 31;

    const float* QH = g_QH + (size_t)bh * SS * DFF;
    const float* KH = g_KH + (size_t)bh * SS * DFF;
    const float* VH = g_VH + (size_t)bh * SS * DFF;

    #pragma unroll
    for (int u = 0; u < 2; u++) {
        int idx = tid + u * 256;
        int r  = idx >> 4;
        int c4 = (idx & 15) << 2;
        float4 qv = *(const float4*)(QH + (size_t)(q0 + r) * DFF + c4);
        qv.x *= 0.125f; qv.y *= 0.125f; qv.z *= 0.125f; qv.w *= 0.125f;
        *(float4*)(Qs + r * DFF + c4) = qv;
    }

    const int qb1 = (tid >> 5) << 2;
    const int jb1 = (tid & 31) << 2;
    const int njt = (qmax >> 7) + 1;
    for (int jt = 0; jt < njt; jt++) {
        const int j0 = jt << 7;
        __syncthreads();
        {
            int jr  = tid >> 1;
            int df0 = (tid & 1) << 5;
            const float* kp = KH + (size_t)(j0 + jr) * DFF + df0;
            #pragma unroll
            for (int u = 0; u < 8; u++) {
                float4 k4 = *(const float4*)(kp + (u << 2));
                int dfb = df0 + (u << 2);
                KV[(dfb+0)*128 + jr] = k4.x;
                KV[(dfb+1)*128 + jr] = k4.y;
                KV[(dfb+2)*128 + jr] = k4.z;
                KV[(dfb+3)*128 + jr] = k4.w;
            }
        }
        __syncthreads();
        float acc[4][4];
        #pragma unroll
        for (int i = 0; i < 4; i++)
            #pragma unroll
            for (int j = 0; j < 4; j++) acc[i][j] = 0.f;
        #pragma unroll
        for (int df = 0; df < 64; df++) {
            float4 k4 = *(const float4*)(KV + df*128 + jb1);
            float qv0 = Qs[(qb1+0)*64 + df];
            float qv1 = Qs[(qb1+1)*64 + df];
            float qv2 = Qs[(qb1+2)*64 + df];
            float qv3 = Qs[(qb1+3)*64 + df];
            acc[0][0]=fmaf(qv0,k4.x,acc[0][0]); acc[0][1]=fmaf(qv0,k4.y,acc[0][1]);
            acc[0][2]=fmaf(qv0,k4.z,acc[0][2]); acc[0][3]=fmaf(qv0,k4.w,acc[0][3]);
            acc[1][0]=fmaf(qv1,k4.x,acc[1][0]); acc[1][1]=fmaf(qv1,k4.y,acc[1][1]);
            acc[1][2]=fmaf(qv1,k4.z,acc[1][2]); acc[1][3]=fmaf(qv1,k4.w,acc[1][3]);
            acc[2][0]=fmaf(qv2,k4.x,acc[2][0]); acc[2][1]=fmaf(qv2,k4.y,acc[2][1]);
            acc[2][2]=fmaf(qv2,k4.z,acc[2][2]); acc[2][3]=fmaf(qv2,k4.w,acc[2][3]);
            acc[3][0]=fmaf(qv3,k4.x,acc[3][0]); acc[3][1]=fmaf(qv3,k4.y,acc[3][1]);
            acc[3][2]=fmaf(qv3,k4.z,acc[3][2]); acc[3][3]=fmaf(qv3,k4.w,acc[3][3]);
        }
        #pragma unroll
        for (int i = 0; i < 4; i++) {
            float4 o = make_float4(acc[i][0], acc[i][1], acc[i][2], acc[i][3]);
            *(float4*)(SC + (qb1+i)*SCP + j0 + jb1) = o;
        }
    }
    __syncthreads();

    const int lane = tid & 31;
    const int w    = tid >> 5;
    const float gamma = -log1pf(__expf(gammas[h]));
    const int zp = *zero_pad;

    for (int pass = 0; pass < 4; pass++) {
        const int qr = (pass << 3) + w;
        const int qg = q0 + qr;
        float sv[16], pv[16];
        #pragma unroll
        for (int i = 0; i < 16; i++) sv[i] = SC[qr*SCP + (i<<5) + lane];

        float m = -3.0e38f;
        #pragma unroll
        for (int i = 0; i < 16; i++) {
            int j = (i<<5) + lane;
            if (j <= qg) m = fmaxf(m, sv[i]);
        }
        #pragma unroll
        for (int off = 16; off > 0; off >>= 1)
            m = fmaxf(m, __shfl_xor_sync(0xffffffffu, m, off));
        float ssum = 0.f;
        #pragma unroll
        for (int i = 0; i < 16; i++) {
            int j = (i<<5) + lane;
            pv[i] = (j <= qg) ? __expf(sv[i] - m) : 0.f;
            ssum += pv[i];
        }
        #pragma unroll
        for (int off = 16; off > 0; off >>= 1)
            ssum += __shfl_xor_sync(0xffffffffu, ssum, off);
        const float inv1 = 1.f / ssum;

        float carry = 0.f;
        const float* qdrow = qd + ((size_t)b * SS + qg) * SS;
        #pragma unroll
        for (int i = 0; i < 16; i++) {
            int j = (i<<5) + lane;
            float s = pv[i] * inv1;
            #pragma unroll
            for (int off = 1; off < 32; off <<= 1) {
                float t = __shfl_up_sync(0xffffffffu, s, off);
                if (lane >= off) s += t;
            }
            float tot = __shfl_sync(0xffffffffu, s, 31);
            float c = carry + s;
            carry += tot;
            float rem = fmaxf(1.f - c, 0.f);
            float dsc = (j <= qg) ? sqrtf(rem * (float)(qg - j)) : 0.f;
            float qdv = qdrow[j];
            float sig = 1.f / (1.f + __expf(-qdv));
            float diffv = __expf(sig);
            float te = __expf(dsc * gamma * diffv);
            te = fminf(fmaxf(te, 1e-5f), 1e5f);
            pv[i] = (j <= qg) ? sv[i] * te : -3.0e38f;
        }

        float m2 = -3.0e38f;
        #pragma unroll
        for (int i = 0; i < 16; i++) m2 = fmaxf(m2, pv[i]);
        #pragma unroll
        for (int off = 16; off > 0; off >>= 1)
            m2 = fmaxf(m2, __shfl_xor_sync(0xffffffffu, m2, off));
        float sum2 = 0.f;
        #pragma unroll
        for (int i = 0; i < 16; i++) {
            int j = (i<<5) + lane;
            float e = (j <= qg) ? __expf(pv[i] - m2) : 0.f;
            sv[i] = e;
            sum2 += e;
        }
        #pragma unroll
        for (int off = 16; off > 0; off >>= 1)
            sum2 += __shfl_xor_sync(0xffffffffu, sum2, off);
        const float inv2 = 1.f / sum2;
        const bool zrow = (zp != 0) && (qg == 0);
        #pragma unroll
        for (int i = 0; i < 16; i++)
            SC[qr*SCP + (i<<5) + lane] = zrow ? 0.f : sv[i] * inv2;
    }

    const int qb3 = (tid >> 4) << 1;
    const int df3 = (tid & 15) << 2;
    float o0[4] = {0.f,0.f,0.f,0.f};
    float o1[4] = {0.f,0.f,0.f,0.f};
    const int nvt = (qmax >> 6) + 1;
    for (int jt = 0; jt < nvt; jt++) {
        __syncthreads();
        {
            int jr  = tid >> 2;
            int df0 = (tid & 3) << 4;
            const float* vp = VH + (size_t)((jt<<6) + jr) * DFF + df0;
            #pragma unroll
            for (int u = 0; u < 4; u++) {
                float4 v4 = *(const float4*)(vp + (u<<2));
                *(float4*)(KV + jr*72 + df0 + (u<<2)) = v4;
            }
        }
        __syncthreads();
        const int j0 = jt << 6;
        #pragma unroll 8
        for (int jj = 0; jj < 64; jj++) {
            float p0 = SC[(qb3+0)*SCP + j0 + jj];
            float p1 = SC[(qb3+1)*SCP + j0 + jj];
            float4 v4 = *(const float4*)(KV + jj*72 + df3);
            o0[0]=fmaf(p0,v4.x,o0[0]); o0[1]=fmaf(p0,v4.y,o0[1]);
            o0[2]=fmaf(p0,v4.z,o0[2]); o0[3]=fmaf(p0,v4.w,o0[3]);
            o1[0]=fmaf(p1,v4.x,o1[0]); o1[1]=fmaf(p1,v4.y,o1[1]);
            o1[2]=fmaf(p1,v4.z,o1[2]); o1[3]=fmaf(p1,v4.w,o1[3]);
        }
    }
    {
        int qg0 = q0 + qb3;
        float4 a = make_float4(o0[0], o0[1], o0[2], o0[3]);
        float4 c = make_float4(o1[0], o1[1], o1[2], o1[3]);
        *(float4*)(g_CT + ((size_t)(b * SS + qg0    ) * DD) + (h << 6) + df3) = a;
        *(float4*)(g_CT + ((size_t)(b * SS + qg0 + 1) * DD) + (h << 6) + df3) = c;
    }
}

// ---------------------------------------------------------------------------
extern "C" void kernel_launch(void* const* d_in, const int* in_sizes, int n_in,
                              void* d_out, int out_size)
{
    const float* q      = (const float*)d_in[0];
    const float* k      = (const float*)d_in[1];
    const float* v      = (const float*)d_in[2];
    const int*   zero_pad = (const int*)d_in[4];
    const float* qd     = (const float*)d_in[5];
    const float* Wk     = (const float*)d_in[6];
    const float* bk     = (const float*)d_in[7];
    const float* Wv     = (const float*)d_in[8];
    const float* bv     = (const float*)d_in[9];
    const float* Wo     = (const float*)d_in[10];
    const float* bo     = (const float*)d_in[11];
    const float* gammas = (const float*)d_in[12];
    float* out = (float*)d_out;

    const int GEMM_SMEM = 3 * STG_STRIDE;               // 98304 B
    const int ATTN_SMEM = (2048 + 16512 + 8192) * 4;    // 107008 B
    cudaFuncSetAttribute(gemm_mma_kernel<1>,
                         cudaFuncAttributeMaxDynamicSharedMemorySize, GEMM_SMEM);
    cudaFuncSetAttribute(gemm_mma_kernel<0>,
                         cudaFuncAttributeMaxDynamicSharedMemorySize, GEMM_SMEM);
    cudaFuncSetAttribute(akt_attn_kernel,
                         cudaFuncAttributeMaxDynamicSharedMemorySize, ATTN_SMEM);

    const int N_IN = BB * SS * DD;   // 8388608
    const int N_W  = DD * DD;        // 262144

    convert_split<<<N_IN / 2048, 256>>>(q,  0, N_IN);
    convert_split<<<N_IN / 2048, 256>>>(k,  1, N_IN);
    convert_split<<<N_IN / 2048, 256>>>(v,  2, N_IN);
    convert_split<<<N_W  / 2048, 256>>>(Wk, 3, N_W);
    convert_split<<<N_W  / 2048, 256>>>(Wv, 4, N_W);
    convert_split<<<N_W  / 2048, 256>>>(Wo, 5, N_W);

    // QKV projections (z: 0->Q via Wk, 1->K via Wk, 2->V via Wv)
    gemm_mma_kernel<1><<<dim3(128, 4, 3), 256, GEMM_SMEM>>>(bk, bv, nullptr);

    akt_attn_kernel<<<dim3(16, 256), 256, ATTN_SMEM>>>(qd, gammas, zero_pad);

    convert_split<<<N_IN / 2048, 256>>>(nullptr, 6, N_IN);  // g_CT -> splits

    // final projection with Wo
    gemm_mma_kernel<0><<<dim3(128, 4, 1), 256, GEMM_SMEM>>>(bo, nullptr, out);
}